// round 12
// baseline (speedup 1.0000x reference)
#include <cuda_runtime.h>

// OpticalFlowLK 2048x2048 fp32 — shuffle-free, register-rolling (R10 form),
// STRIP=8 + register cap to maximize occupancy. Each lane owns 2 output
// columns, loads its own 5-pixel window (3 aligned float2 cells) per row.
// Horizontal-first box sums; vertical 3-sum via rolling registers.

#define IMH 2048
#define IMW 2048
#define CELLS 1024            // float2 cells per image row
#define STRIP 8
#define WPB 4

struct Row5 { float e[5]; float f[5]; };   // E=P+N, F=N-P at 5 pixel cols
struct H10 { float v[10]; };               // xx0,xx1,yy0,yy1,xy0,xy1,xt0,xt1,yt0,yt1

// Gradients scaled 2x vs reference (0.5 dropped): all tensor sums scale 4x
// uniformly, so u, v and the det==0 set are unchanged.

__device__ __forceinline__ int rowclamp(int r) {
    if (r < 0) return 0;
    if (r == IMH) return IMH - 2;   // reflect-after
    if (r > IMH) return 0;
    return r;
}
__device__ __forceinline__ int clampcol(int c) {
    if (c < 0) return 0;
    if (c == IMW) return IMW - 2;   // reflect-after
    if (c > IMW) return 0;
    return c;
}

__device__ __forceinline__ Row5 makeRow(float2 Lp, float2 Mp, float2 Rp,
                                        float2 Ln, float2 Mn, float2 Rn) {
    float p[5] = {Lp.y, Mp.x, Mp.y, Rp.x, Rp.y};
    float n[5] = {Ln.y, Mn.x, Mn.y, Rn.x, Rn.y};
    Row5 r;
#pragma unroll
    for (int k = 0; k < 5; k++) { r.e[k] = p[k] + n[k]; r.f[k] = n[k] - p[k]; }
    return r;
}

// Products for one product row at 4 cols + immediate horizontal 3-sums.
__device__ __forceinline__ H10 prodH(const Row5& a, const Row5& b) {
    float S[5], D[5], T[5];
#pragma unroll
    for (int k = 0; k < 5; k++) {
        S[k] = a.e[k] + b.e[k];
        D[k] = b.e[k] - a.e[k];
        T[k] = a.f[k] + b.f[k];
    }
    float xx[4], yy[4], xy[4], xt[4], yt[4];
#pragma unroll
    for (int k = 0; k < 4; k++) {
        float rx = S[k + 1] - S[k];
        float ry = D[k] + D[k + 1];
        float rt = T[k] + T[k + 1];
        xx[k] = rx * rx; yy[k] = ry * ry; xy[k] = rx * ry;
        xt[k] = rt * rx; yt[k] = rt * ry;
    }
    H10 h;
    float m;
    m = xx[1] + xx[2]; h.v[0] = xx[0] + m; h.v[1] = m + xx[3];
    m = yy[1] + yy[2]; h.v[2] = yy[0] + m; h.v[3] = m + yy[3];
    m = xy[1] + xy[2]; h.v[4] = xy[0] + m; h.v[5] = m + xy[3];
    m = xt[1] + xt[2]; h.v[6] = xt[0] + m; h.v[7] = m + xt[3];
    m = yt[1] + yt[2]; h.v[8] = yt[0] + m; h.v[9] = m + yt[3];
    return h;
}

// Masked variant (per-product-col validity, incl. row validity).
__device__ __forceinline__ H10 prodHm(const Row5& a, const Row5& b,
                                      const bool* valid) {
    float S[5], D[5], T[5];
#pragma unroll
    for (int k = 0; k < 5; k++) {
        S[k] = a.e[k] + b.e[k];
        D[k] = b.e[k] - a.e[k];
        T[k] = a.f[k] + b.f[k];
    }
    float xx[4], yy[4], xy[4], xt[4], yt[4];
#pragma unroll
    for (int k = 0; k < 4; k++) {
        float rx = S[k + 1] - S[k];
        float ry = D[k] + D[k + 1];
        float rt = T[k] + T[k + 1];
        xx[k] = valid[k] ? rx * rx : 0.f;
        yy[k] = valid[k] ? ry * ry : 0.f;
        xy[k] = valid[k] ? rx * ry : 0.f;
        xt[k] = valid[k] ? rt * rx : 0.f;
        yt[k] = valid[k] ? rt * ry : 0.f;
    }
    H10 h;
    float m;
    m = xx[1] + xx[2]; h.v[0] = xx[0] + m; h.v[1] = m + xx[3];
    m = yy[1] + yy[2]; h.v[2] = yy[0] + m; h.v[3] = m + yy[3];
    m = xy[1] + xy[2]; h.v[4] = xy[0] + m; h.v[5] = m + xy[3];
    m = xt[1] + xt[2]; h.v[6] = xt[0] + m; h.v[7] = m + xt[3];
    m = yt[1] + yt[2]; h.v[8] = yt[0] + m; h.v[9] = m + yt[3];
    return h;
}

__device__ __forceinline__ void solve1(float Sxx, float Syy, float Sxy,
                                       float Sxt, float Syt,
                                       float& u, float& v) {
    float det = Sxx * Syy - Sxy * Sxy;
    u = 0.f; v = 0.f;
    if (det != 0.f) {
        float inv = __fdividef(1.0f, det);
        u = (Syy * Sxt - Sxy * Syt) * inv;
        v = (Sxx * Syt - Sxy * Sxt) * inv;
    }
}

__device__ __forceinline__ void finish(const H10& a, const H10& b, const H10& c,
                                       float2& u2, float2& v2) {
    float s[10];
#pragma unroll
    for (int k = 0; k < 10; k++) s[k] = a.v[k] + b.v[k] + c.v[k];
    solve1(s[0], s[2], s[4], s[6], s[8], u2.x, v2.x);
    solve1(s[1], s[3], s[5], s[7], s[9], u2.y, v2.y);
}

__device__ __forceinline__ Row5 loadRowE(const float* __restrict__ prev,
                                         const float* __restrict__ next,
                                         int rr, const int* pc) {
    float p[5], n[5];
    size_t rb = (size_t)rr * IMW;
#pragma unroll
    for (int k = 0; k < 5; k++) { p[k] = prev[rb + pc[k]]; n[k] = next[rb + pc[k]]; }
    Row5 r;
#pragma unroll
    for (int k = 0; k < 5; k++) { r.e[k] = p[k] + n[k]; r.f[k] = n[k] - p[k]; }
    return r;
}

__global__ __launch_bounds__(32 * WPB, 9)   // cap regs at 56 -> 36-warp occupancy
void lk_flow_kernel(const float* __restrict__ prev,
                    const float* __restrict__ next,
                    float* __restrict__ out) {
    const int lane = threadIdx.x;
    const int g = blockIdx.x * WPB + threadIdx.y;   // column group 0..31
    const int j = g * 32 + lane;                    // float2 cell index 0..1023
    const int c0 = 2 * j;                           // output columns c0, c0+1
    const int r0 = blockIdx.y * STRIP;

    float2* outU = reinterpret_cast<float2*>(out);
    float2* outV = reinterpret_cast<float2*>(out + (size_t)IMH * IMW);

    const bool interior = (g >= 1) && (g <= 30) &&
                          (blockIdx.y >= 1) && (blockIdx.y <= (IMH / STRIP) - 2);

    if (interior) {
        // ---------------- FAST PATH: branchless, shuffle-free ----------------
        const float2* P2 = reinterpret_cast<const float2*>(prev)
                           + (size_t)(r0 - 1) * CELLS + (j - 1);
        const float2* N2 = reinterpret_cast<const float2*>(next)
                           + (size_t)(r0 - 1) * CELLS + (j - 1);

        Row5 rm = makeRow(P2[0], P2[1], P2[2], N2[0], N2[1], N2[2]);  // row r0-1
        P2 += CELLS; N2 += CELLS;
        Row5 rc = makeRow(P2[0], P2[1], P2[2], N2[0], N2[1], N2[2]);  // row r0
        P2 += CELLS; N2 += CELLS;
        Row5 ra = makeRow(P2[0], P2[1], P2[2], N2[0], N2[1], N2[2]);  // row r0+1
        P2 += CELLS; N2 += CELLS;                                     // -> row r0+2

        H10 h0 = prodH(rm, rc);   // product row r0-1
        H10 h1 = prodH(rc, ra);   // product row r0

        size_t o = (size_t)r0 * CELLS + j;

        #pragma unroll 4
        for (int it = 0; it < STRIP; ++it) {
            float2 Lp = P2[0], Mp = P2[1], Rp = P2[2];
            float2 Ln = N2[0], Mn = N2[1], Rn = N2[2];
            P2 += CELLS; N2 += CELLS;

            Row5 rb = makeRow(Lp, Mp, Rp, Ln, Mn, Rn);
            H10 h2 = prodH(ra, rb);              // product row r+1

            float2 u2, v2;
            finish(h0, h1, h2, u2, v2);
            outU[o] = u2;
            outV[o] = v2;
            o += CELLS;

            h0 = h1; h1 = h2; ra = rb;
        }
        return;
    }

    // ---------------- EDGE PATH: clamped scalar loads + validity ----------------
    int pc[5];
    bool cvp[4];
#pragma unroll
    for (int k = 0; k < 5; k++) pc[k] = clampcol(c0 - 1 + k);
#pragma unroll
    for (int k = 0; k < 4; k++) {
        int c = c0 - 1 + k;
        cvp[k] = (c >= 0) && (c < IMW);
    }

    Row5 rm = loadRowE(prev, next, rowclamp(r0 - 1), pc);
    Row5 rc = loadRowE(prev, next, r0, pc);
    Row5 ra = loadRowE(prev, next, r0 + 1, pc);

    bool vm[4];
#pragma unroll
    for (int k = 0; k < 4; k++) vm[k] = cvp[k] && (r0 > 0);
    H10 h0 = prodHm(rm, rc, vm);    // product row r0-1
    H10 h1 = prodHm(rc, ra, cvp);   // product row r0 (always in range)

    size_t o = (size_t)r0 * CELLS + j;

    for (int r = r0; r < r0 + STRIP; ++r) {
        Row5 rb = loadRowE(prev, next, rowclamp(r + 2), pc);

        bool vb[4];
        const bool rv = (r + 1 < IMH);
#pragma unroll
        for (int k = 0; k < 4; k++) vb[k] = cvp[k] && rv;
        H10 h2 = prodHm(ra, rb, vb);            // product row r+1

        float2 u2, v2;
        finish(h0, h1, h2, u2, v2);
        if (r == 0) { u2 = make_float2(0.f, 0.f); v2 = make_float2(0.f, 0.f); }
        if (c0 == 0) { u2.x = 0.f; v2.x = 0.f; }

        outU[o] = u2;
        outV[o] = v2;
        o += CELLS;

        h0 = h1; h1 = h2; ra = rb;
    }
}

extern "C" void kernel_launch(void* const* d_in, const int* in_sizes, int n_in,
                              void* d_out, int out_size) {
    const float* prev = (const float*)d_in[0];
    const float* next = (const float*)d_in[1];
    float* out = (float*)d_out;
    dim3 block(32, WPB, 1);
    dim3 grid(32 / WPB, IMH / STRIP, 1);
    lk_flow_kernel<<<grid, block>>>(prev, next, out);
}

// round 13
// speedup vs baseline: 1.1920x; 1.1920x over previous
#include <cuda_runtime.h>

// OpticalFlowLK 2048x2048 fp32 — shuffle-free, register-rolling (R10 form),
// STRIP=8 for doubled warp supply, natural register allocation (no cap).
// Each lane owns 2 output columns, loads its own 5-pixel window (3 aligned
// float2 cells) per row. Horizontal-first box sums; vertical rolling sums.

#define IMH 2048
#define IMW 2048
#define CELLS 1024            // float2 cells per image row
#define STRIP 8
#define WPB 4

struct Row5 { float e[5]; float f[5]; };   // E=P+N, F=N-P at 5 pixel cols
struct H10 { float v[10]; };               // xx0,xx1,yy0,yy1,xy0,xy1,xt0,xt1,yt0,yt1

// Gradients scaled 2x vs reference (0.5 dropped): all tensor sums scale 4x
// uniformly, so u, v and the det==0 set are unchanged.

__device__ __forceinline__ int rowclamp(int r) {
    if (r < 0) return 0;
    if (r == IMH) return IMH - 2;   // reflect-after
    if (r > IMH) return 0;
    return r;
}
__device__ __forceinline__ int clampcol(int c) {
    if (c < 0) return 0;
    if (c == IMW) return IMW - 2;   // reflect-after
    if (c > IMW) return 0;
    return c;
}

__device__ __forceinline__ Row5 makeRow(float2 Lp, float2 Mp, float2 Rp,
                                        float2 Ln, float2 Mn, float2 Rn) {
    float p[5] = {Lp.y, Mp.x, Mp.y, Rp.x, Rp.y};
    float n[5] = {Ln.y, Mn.x, Mn.y, Rn.x, Rn.y};
    Row5 r;
#pragma unroll
    for (int k = 0; k < 5; k++) { r.e[k] = p[k] + n[k]; r.f[k] = n[k] - p[k]; }
    return r;
}

// Products for one product row at 4 cols + immediate horizontal 3-sums.
__device__ __forceinline__ H10 prodH(const Row5& a, const Row5& b) {
    float S[5], D[5], T[5];
#pragma unroll
    for (int k = 0; k < 5; k++) {
        S[k] = a.e[k] + b.e[k];
        D[k] = b.e[k] - a.e[k];
        T[k] = a.f[k] + b.f[k];
    }
    float xx[4], yy[4], xy[4], xt[4], yt[4];
#pragma unroll
    for (int k = 0; k < 4; k++) {
        float rx = S[k + 1] - S[k];
        float ry = D[k] + D[k + 1];
        float rt = T[k] + T[k + 1];
        xx[k] = rx * rx; yy[k] = ry * ry; xy[k] = rx * ry;
        xt[k] = rt * rx; yt[k] = rt * ry;
    }
    H10 h;
    float m;
    m = xx[1] + xx[2]; h.v[0] = xx[0] + m; h.v[1] = m + xx[3];
    m = yy[1] + yy[2]; h.v[2] = yy[0] + m; h.v[3] = m + yy[3];
    m = xy[1] + xy[2]; h.v[4] = xy[0] + m; h.v[5] = m + xy[3];
    m = xt[1] + xt[2]; h.v[6] = xt[0] + m; h.v[7] = m + xt[3];
    m = yt[1] + yt[2]; h.v[8] = yt[0] + m; h.v[9] = m + yt[3];
    return h;
}

// Masked variant (per-product-col validity, incl. row validity).
__device__ __forceinline__ H10 prodHm(const Row5& a, const Row5& b,
                                      const bool* valid) {
    float S[5], D[5], T[5];
#pragma unroll
    for (int k = 0; k < 5; k++) {
        S[k] = a.e[k] + b.e[k];
        D[k] = b.e[k] - a.e[k];
        T[k] = a.f[k] + b.f[k];
    }
    float xx[4], yy[4], xy[4], xt[4], yt[4];
#pragma unroll
    for (int k = 0; k < 4; k++) {
        float rx = S[k + 1] - S[k];
        float ry = D[k] + D[k + 1];
        float rt = T[k] + T[k + 1];
        xx[k] = valid[k] ? rx * rx : 0.f;
        yy[k] = valid[k] ? ry * ry : 0.f;
        xy[k] = valid[k] ? rx * ry : 0.f;
        xt[k] = valid[k] ? rt * rx : 0.f;
        yt[k] = valid[k] ? rt * ry : 0.f;
    }
    H10 h;
    float m;
    m = xx[1] + xx[2]; h.v[0] = xx[0] + m; h.v[1] = m + xx[3];
    m = yy[1] + yy[2]; h.v[2] = yy[0] + m; h.v[3] = m + yy[3];
    m = xy[1] + xy[2]; h.v[4] = xy[0] + m; h.v[5] = m + xy[3];
    m = xt[1] + xt[2]; h.v[6] = xt[0] + m; h.v[7] = m + xt[3];
    m = yt[1] + yt[2]; h.v[8] = yt[0] + m; h.v[9] = m + yt[3];
    return h;
}

__device__ __forceinline__ void solve1(float Sxx, float Syy, float Sxy,
                                       float Sxt, float Syt,
                                       float& u, float& v) {
    float det = Sxx * Syy - Sxy * Sxy;
    u = 0.f; v = 0.f;
    if (det != 0.f) {
        float inv = __fdividef(1.0f, det);
        u = (Syy * Sxt - Sxy * Syt) * inv;
        v = (Sxx * Syt - Sxy * Sxt) * inv;
    }
}

__device__ __forceinline__ void finish(const H10& a, const H10& b, const H10& c,
                                       float2& u2, float2& v2) {
    float s[10];
#pragma unroll
    for (int k = 0; k < 10; k++) s[k] = a.v[k] + b.v[k] + c.v[k];
    solve1(s[0], s[2], s[4], s[6], s[8], u2.x, v2.x);
    solve1(s[1], s[3], s[5], s[7], s[9], u2.y, v2.y);
}

__device__ __forceinline__ Row5 loadRowE(const float* __restrict__ prev,
                                         const float* __restrict__ next,
                                         int rr, const int* pc) {
    float p[5], n[5];
    size_t rb = (size_t)rr * IMW;
#pragma unroll
    for (int k = 0; k < 5; k++) { p[k] = prev[rb + pc[k]]; n[k] = next[rb + pc[k]]; }
    Row5 r;
#pragma unroll
    for (int k = 0; k < 5; k++) { r.e[k] = p[k] + n[k]; r.f[k] = n[k] - p[k]; }
    return r;
}

__global__ __launch_bounds__(32 * WPB)
void lk_flow_kernel(const float* __restrict__ prev,
                    const float* __restrict__ next,
                    float* __restrict__ out) {
    const int lane = threadIdx.x;
    const int g = blockIdx.x * WPB + threadIdx.y;   // column group 0..31
    const int j = g * 32 + lane;                    // float2 cell index 0..1023
    const int c0 = 2 * j;                           // output columns c0, c0+1
    const int r0 = blockIdx.y * STRIP;

    float2* outU = reinterpret_cast<float2*>(out);
    float2* outV = reinterpret_cast<float2*>(out + (size_t)IMH * IMW);

    const bool interior = (g >= 1) && (g <= 30) &&
                          (blockIdx.y >= 1) && (blockIdx.y <= (IMH / STRIP) - 2);

    if (interior) {
        // ---------------- FAST PATH: branchless, shuffle-free ----------------
        const float2* P2 = reinterpret_cast<const float2*>(prev)
                           + (size_t)(r0 - 1) * CELLS + (j - 1);
        const float2* N2 = reinterpret_cast<const float2*>(next)
                           + (size_t)(r0 - 1) * CELLS + (j - 1);

        Row5 rm = makeRow(P2[0], P2[1], P2[2], N2[0], N2[1], N2[2]);  // row r0-1
        P2 += CELLS; N2 += CELLS;
        Row5 rc = makeRow(P2[0], P2[1], P2[2], N2[0], N2[1], N2[2]);  // row r0
        P2 += CELLS; N2 += CELLS;
        Row5 ra = makeRow(P2[0], P2[1], P2[2], N2[0], N2[1], N2[2]);  // row r0+1
        P2 += CELLS; N2 += CELLS;                                     // -> row r0+2

        H10 h0 = prodH(rm, rc);   // product row r0-1
        H10 h1 = prodH(rc, ra);   // product row r0

        size_t o = (size_t)r0 * CELLS + j;

        #pragma unroll 4
        for (int it = 0; it < STRIP; ++it) {
            float2 Lp = P2[0], Mp = P2[1], Rp = P2[2];
            float2 Ln = N2[0], Mn = N2[1], Rn = N2[2];
            P2 += CELLS; N2 += CELLS;

            Row5 rb = makeRow(Lp, Mp, Rp, Ln, Mn, Rn);
            H10 h2 = prodH(ra, rb);              // product row r+1

            float2 u2, v2;
            finish(h0, h1, h2, u2, v2);
            outU[o] = u2;
            outV[o] = v2;
            o += CELLS;

            h0 = h1; h1 = h2; ra = rb;
        }
        return;
    }

    // ---------------- EDGE PATH: clamped scalar loads + validity ----------------
    int pc[5];
    bool cvp[4];
#pragma unroll
    for (int k = 0; k < 5; k++) pc[k] = clampcol(c0 - 1 + k);
#pragma unroll
    for (int k = 0; k < 4; k++) {
        int c = c0 - 1 + k;
        cvp[k] = (c >= 0) && (c < IMW);
    }

    Row5 rm = loadRowE(prev, next, rowclamp(r0 - 1), pc);
    Row5 rc = loadRowE(prev, next, r0, pc);
    Row5 ra = loadRowE(prev, next, r0 + 1, pc);

    bool vm[4];
#pragma unroll
    for (int k = 0; k < 4; k++) vm[k] = cvp[k] && (r0 > 0);
    H10 h0 = prodHm(rm, rc, vm);    // product row r0-1
    H10 h1 = prodHm(rc, ra, cvp);   // product row r0 (always in range)

    size_t o = (size_t)r0 * CELLS + j;

    for (int r = r0; r < r0 + STRIP; ++r) {
        Row5 rb = loadRowE(prev, next, rowclamp(r + 2), pc);

        bool vb[4];
        const bool rv = (r + 1 < IMH);
#pragma unroll
        for (int k = 0; k < 4; k++) vb[k] = cvp[k] && rv;
        H10 h2 = prodHm(ra, rb, vb);            // product row r+1

        float2 u2, v2;
        finish(h0, h1, h2, u2, v2);
        if (r == 0) { u2 = make_float2(0.f, 0.f); v2 = make_float2(0.f, 0.f); }
        if (c0 == 0) { u2.x = 0.f; v2.x = 0.f; }

        outU[o] = u2;
        outV[o] = v2;
        o += CELLS;

        h0 = h1; h1 = h2; ra = rb;
    }
}

extern "C" void kernel_launch(void* const* d_in, const int* in_sizes, int n_in,
                              void* d_out, int out_size) {
    const float* prev = (const float*)d_in[0];
    const float* next = (const float*)d_in[1];
    float* out = (float*)d_out;
    dim3 block(32, WPB, 1);
    dim3 grid(32 / WPB, IMH / STRIP, 1);
    lk_flow_kernel<<<grid, block>>>(prev, next, out);
}